// round 6
// baseline (speedup 1.0000x reference)
#include <cuda_runtime.h>

#define NL 16
#define NE 10
#define NC 128
#define NB_TOT 8192
#define NBASIS 968      // 16 linear + 136 pairs + 816 triples (Horner order)
#define MROW 12         // 10 floats padded to 12 (48B rows, 16B aligned)
#define TPB 128
#define ROWS 4

typedef unsigned long long ull;

// Precomputed per-channel basis->element matrix in Horner traversal order.
__device__ __align__(16) static float g_M[(size_t)NC * NBASIS * MROW];

__device__ __forceinline__ int id3(int a, int b, int d) { return ((a*NL + b)*NL + d) * 23; }

// ---------------------------------------------------------------------------
// build_M: one thread per (m, c). Decodes Horner-order row index m into
// (type, p, q, i), symmetrizes U over index permutations, contracts with W.
// Horner order: for p { M1(p); for q>=p { M2(p,q); for i>=q { M3(p,q,i) } } }
// ---------------------------------------------------------------------------
__global__ void build_M_kernel(const float* __restrict__ U1, const float* __restrict__ U2,
                               const float* __restrict__ U3, const float* __restrict__ W1,
                               const float* __restrict__ W2, const float* __restrict__ W3) {
    int t = blockIdx.x * blockDim.x + threadIdx.x;
    if (t >= NBASIS * NC) return;
    int m = t >> 7;
    int c = t & (NC - 1);

    // Decode Horner position.
    int p = 0;
    for (;;) {
        int np = NL - p;                         // #q values
        int blk = 1 + np + np * (np + 1) / 2;    // M1 + per-q (M2 + triples)
        if (m < blk) break;
        m -= blk; p++;
    }
    int type, q = 0, i = 0;
    if (m == 0) {
        type = 1;
    } else {
        m -= 1;
        q = p;
        for (;;) {
            int blk = 1 + (NL - q);
            if (m < blk) break;
            m -= blk; q++;
        }
        if (m == 0) type = 2;
        else { type = 3; i = q + (m - 1); }
    }

    float row[NE];
    if (type == 1) {
        float u = U1[p];                          // K1 == 1
        #pragma unroll
        for (int e = 0; e < NE; e++) row[e] = u * W1[e*NC + c];
    } else if (type == 2) {
        float s[4];
        #pragma unroll
        for (int k = 0; k < 4; k++) {
            float v = U2[(p*NL + q)*4 + k];
            if (p != q) v += U2[(q*NL + p)*4 + k];
            s[k] = v;
        }
        #pragma unroll
        for (int e = 0; e < NE; e++) {
            float a = 0.f;
            #pragma unroll
            for (int k = 0; k < 4; k++) a += s[k] * W2[(e*4 + k)*NC + c];
            row[e] = a;
        }
    } else {
        float s[23];
        for (int k = 0; k < 23; k++) {
            float v = U3[id3(p,q,i) + k];
            if (p < q && q < i) {
                v += U3[id3(p,i,q)+k] + U3[id3(q,p,i)+k] + U3[id3(q,i,p)+k]
                   + U3[id3(i,p,q)+k] + U3[id3(i,q,p)+k];
            } else if (p == q && q < i) {
                v += U3[id3(p,i,p)+k] + U3[id3(i,p,p)+k];
            } else if (p < q && q == i) {
                v += U3[id3(q,p,q)+k] + U3[id3(q,q,p)+k];
            }
            s[k] = v;
        }
        for (int e = 0; e < NE; e++) {
            float a = 0.f;
            for (int k = 0; k < 23; k++) a += s[k] * W3[(e*23 + k)*NC + c];
            row[e] = a;
        }
    }

    int mrow = t >> 7;
    float* dst = g_M + ((size_t)c * NBASIS + mrow) * MROW;
    #pragma unroll
    for (int e = 0; e < NE; e++) dst[e] = row[e];
    dst[10] = 0.f;
    dst[11] = 0.f;
}

// ---------------------------------------------------------------------------
// Packed fp32x2 helpers.
// ---------------------------------------------------------------------------
__device__ __forceinline__ void ffma2(ull& d, ull a, ull b) {
    asm("fma.rn.f32x2 %0, %1, %2, %0;" : "+l"(d) : "l"(a), "l"(b));
}
__device__ __forceinline__ ull dup2(float v) {
    ull r;
    asm("mov.b64 %0, {%1, %1};" : "=l"(r) : "f"(v));
    return r;
}

struct Row { ull a, b, c, d, e; };

__device__ __forceinline__ Row load_row(const float* mp) {
    ulonglong2 u0 = *reinterpret_cast<const ulonglong2*>(mp);
    ulonglong2 u1 = *reinterpret_cast<const ulonglong2*>(mp + 4);
    ull u2 = *reinterpret_cast<const ull*>(mp + 8);
    Row r; r.a = u0.x; r.b = u0.y; r.c = u1.x; r.d = u1.y; r.e = u2;
    return r;
}
__device__ __forceinline__ void fma_row(Row& acc, ull d, const Row& m) {
    ffma2(acc.a, d, m.a);
    ffma2(acc.b, d, m.b);
    ffma2(acc.c, d, m.c);
    ffma2(acc.d, d, m.d);
    ffma2(acc.e, d, m.e);
}
__device__ __forceinline__ void zero_row(Row& r) {
    r.a = r.b = r.c = r.d = r.e = 0ull;
}

__device__ __forceinline__ void epilogue_row(const Row& a, int b, int c,
                                             const float* __restrict__ y,
                                             float* __restrict__ out) {
    const float* yb = y + (size_t)b * NE;
    ull v[5] = {a.a, a.b, a.c, a.d, a.e};
    float res = 0.f;
    #pragma unroll
    for (int k = 0; k < 5; k++) {
        float lo, hi;
        asm("mov.b64 {%0, %1}, %2;" : "=f"(lo), "=f"(hi) : "l"(v[k]));
        res += lo * yb[2*k];
        res += hi * yb[2*k + 1];
    }
    out[(size_t)b * NC + c] = res;
}

// ---------------------------------------------------------------------------
// Main kernel: fully unrolled Horner evaluation. Each thread: 4 b-rows, one
// channel c. x lives in registers; M staged in static shared, walked
// sequentially. ROWS=4 amortizes each broadcast M-row read over 20 FFMA2,
// balancing smem-crossbar bandwidth against the FMA pipe.
// ---------------------------------------------------------------------------
__global__ __launch_bounds__(TPB, 3)
void contract_kernel(const float* __restrict__ x, const float* __restrict__ y,
                     float* __restrict__ out) {
    __shared__ __align__(16) float sM[NBASIS * MROW];

    const int c   = blockIdx.y;
    const int b0  = blockIdx.x * (TPB * ROWS);
    const int tid = threadIdx.x;

    // Stage M[c] into shared (float4, broadcast-reused by all warps).
    {
        const float4* src = reinterpret_cast<const float4*>(g_M + (size_t)c * NBASIS * MROW);
        float4* dst = reinterpret_cast<float4*>(sM);
        const int n4 = NBASIS * MROW / 4;   // 2904
        for (int j = tid; j < n4; j += TPB) dst[j] = src[j];
    }

    // Load the thread's four x rows straight into registers.
    float xv[ROWS][NL];
    #pragma unroll
    for (int r = 0; r < ROWS; r++) {
        const float4* xr = reinterpret_cast<const float4*>(
            x + ((size_t)(b0 + r * TPB + tid) * NC + c) * NL);
        #pragma unroll
        for (int j = 0; j < 4; j++) {
            float4 v = xr[j];
            xv[r][4*j+0] = v.x; xv[r][4*j+1] = v.y;
            xv[r][4*j+2] = v.z; xv[r][4*j+3] = v.w;
        }
    }
    __syncthreads();

    Row acc[ROWS];
    #pragma unroll
    for (int r = 0; r < ROWS; r++) zero_row(acc[r]);

    const float* mp = sM;
    #pragma unroll
    for (int p = 0; p < NL; p++) {
        Row ap[ROWS];
        {
            Row m1 = load_row(mp);       // M1[p]
            mp += MROW;
            #pragma unroll
            for (int r = 0; r < ROWS; r++) ap[r] = m1;
        }
        #pragma unroll
        for (int q = p; q < NL; q++) {
            Row s[ROWS];
            {
                Row m2 = load_row(mp);   // M2[p,q]
                mp += MROW;
                #pragma unroll
                for (int r = 0; r < ROWS; r++) s[r] = m2;
            }
            #pragma unroll
            for (int i = q; i < NL; i++) {
                Row m3 = load_row(mp);
                mp += MROW;
                #pragma unroll
                for (int r = 0; r < ROWS; r++)
                    fma_row(s[r], dup2(xv[r][i]), m3);
            }
            #pragma unroll
            for (int r = 0; r < ROWS; r++)
                fma_row(ap[r], dup2(xv[r][q]), s[r]);
        }
        #pragma unroll
        for (int r = 0; r < ROWS; r++)
            fma_row(acc[r], dup2(xv[r][p]), ap[r]);
    }

    #pragma unroll
    for (int r = 0; r < ROWS; r++)
        epilogue_row(acc[r], b0 + r * TPB + tid, c, y, out);
}

// ---------------------------------------------------------------------------
extern "C" void kernel_launch(void* const* d_in, const int* in_sizes, int n_in,
                              void* d_out, int out_size) {
    const float *x = 0, *y = 0, *U1 = 0, *U2 = 0, *U3 = 0, *W1 = 0, *W2 = 0, *W3 = 0;
    for (int i = 0; i < n_in; i++) {
        const float* p = (const float*)d_in[i];
        switch (in_sizes[i]) {
            case 8192 * 128 * 16:   x  = p; break;   // (B,C,L)
            case 8192 * 10:         y  = p; break;   // (B,E)
            case 16:                U1 = p; break;   // (L,K1)
            case 16 * 16 * 4:       U2 = p; break;   // (L,L,K2)
            case 16 * 16 * 16 * 23: U3 = p; break;   // (L,L,L,K3)
            case 10 * 1 * 128:      W1 = p; break;   // (E,K1,C)
            case 10 * 4 * 128:      W2 = p; break;   // (E,K2,C)
            case 10 * 23 * 128:     W3 = p; break;   // (E,K3,C)
        }
    }

    const int tot = NBASIS * NC;
    build_M_kernel<<<(tot + 255) / 256, 256>>>(U1, U2, U3, W1, W2, W3);

    dim3 grid(NB_TOT / (TPB * ROWS), NC);   // (16, 128)
    contract_kernel<<<grid, TPB>>>(x, y, (float*)d_out);
}

// round 7
// speedup vs baseline: 1.0783x; 1.0783x over previous
#include <cuda_runtime.h>

#define NL 16
#define NE 10
#define NC 128
#define NB_TOT 8192
#define NBASIS 968      // 16 linear + 136 pairs + 816 triples (Horner order)
#define MROW 12         // 10 floats padded to 12 (48B rows, 16B aligned)
#define TPB 128
#define ROWS 4

typedef unsigned long long ull;

// Precomputed per-channel basis->element matrix in Horner traversal order.
__device__ __align__(16) static float g_M[(size_t)NC * NBASIS * MROW];

__device__ __forceinline__ int id3(int a, int b, int d) { return ((a*NL + b)*NL + d) * 23; }

// ---------------------------------------------------------------------------
// build_M: one thread per (m, c). Decodes Horner-order row index m into
// (type, p, q, i), symmetrizes U over index permutations, contracts with W.
// Horner order: for p { M1(p); for q>=p { M2(p,q); for i>=q { M3(p,q,i) } } }
// ---------------------------------------------------------------------------
__global__ void build_M_kernel(const float* __restrict__ U1, const float* __restrict__ U2,
                               const float* __restrict__ U3, const float* __restrict__ W1,
                               const float* __restrict__ W2, const float* __restrict__ W3) {
    int t = blockIdx.x * blockDim.x + threadIdx.x;
    if (t >= NBASIS * NC) return;
    int m = t >> 7;
    int c = t & (NC - 1);

    // Decode Horner position.
    int p = 0;
    for (;;) {
        int np = NL - p;                         // #q values
        int blk = 1 + np + np * (np + 1) / 2;    // M1 + per-q (M2 + triples)
        if (m < blk) break;
        m -= blk; p++;
    }
    int type, q = 0, i = 0;
    if (m == 0) {
        type = 1;
    } else {
        m -= 1;
        q = p;
        for (;;) {
            int blk = 1 + (NL - q);
            if (m < blk) break;
            m -= blk; q++;
        }
        if (m == 0) type = 2;
        else { type = 3; i = q + (m - 1); }
    }

    float row[NE];
    if (type == 1) {
        float u = U1[p];                          // K1 == 1
        #pragma unroll
        for (int e = 0; e < NE; e++) row[e] = u * W1[e*NC + c];
    } else if (type == 2) {
        float s[4];
        #pragma unroll
        for (int k = 0; k < 4; k++) {
            float v = U2[(p*NL + q)*4 + k];
            if (p != q) v += U2[(q*NL + p)*4 + k];
            s[k] = v;
        }
        #pragma unroll
        for (int e = 0; e < NE; e++) {
            float a = 0.f;
            #pragma unroll
            for (int k = 0; k < 4; k++) a += s[k] * W2[(e*4 + k)*NC + c];
            row[e] = a;
        }
    } else {
        float s[23];
        for (int k = 0; k < 23; k++) {
            float v = U3[id3(p,q,i) + k];
            if (p < q && q < i) {
                v += U3[id3(p,i,q)+k] + U3[id3(q,p,i)+k] + U3[id3(q,i,p)+k]
                   + U3[id3(i,p,q)+k] + U3[id3(i,q,p)+k];
            } else if (p == q && q < i) {
                v += U3[id3(p,i,p)+k] + U3[id3(i,p,p)+k];
            } else if (p < q && q == i) {
                v += U3[id3(q,p,q)+k] + U3[id3(q,q,p)+k];
            }
            s[k] = v;
        }
        for (int e = 0; e < NE; e++) {
            float a = 0.f;
            for (int k = 0; k < 23; k++) a += s[k] * W3[(e*23 + k)*NC + c];
            row[e] = a;
        }
    }

    int mrow = t >> 7;
    float* dst = g_M + ((size_t)c * NBASIS + mrow) * MROW;
    #pragma unroll
    for (int e = 0; e < NE; e++) dst[e] = row[e];
    dst[10] = 0.f;
    dst[11] = 0.f;
}

// ---------------------------------------------------------------------------
// Packed fp32x2 helpers.
// ---------------------------------------------------------------------------
__device__ __forceinline__ void ffma2(ull& d, ull a, ull b) {
    asm("fma.rn.f32x2 %0, %1, %2, %0;" : "+l"(d) : "l"(a), "l"(b));
}
__device__ __forceinline__ ull dup2(float v) {
    ull r;
    asm("mov.b64 %0, {%1, %1};" : "=l"(r) : "f"(v));
    return r;
}

struct Row { ull a, b, c, d, e; };

__device__ __forceinline__ Row load_row(const float* mp) {
    ulonglong2 u0 = *reinterpret_cast<const ulonglong2*>(mp);
    ulonglong2 u1 = *reinterpret_cast<const ulonglong2*>(mp + 4);
    ull u2 = *reinterpret_cast<const ull*>(mp + 8);
    Row r; r.a = u0.x; r.b = u0.y; r.c = u1.x; r.d = u1.y; r.e = u2;
    return r;
}
__device__ __forceinline__ void fma_row(Row& acc, ull d, const Row& m) {
    ffma2(acc.a, d, m.a);
    ffma2(acc.b, d, m.b);
    ffma2(acc.c, d, m.c);
    ffma2(acc.d, d, m.d);
    ffma2(acc.e, d, m.e);
}
__device__ __forceinline__ void zero_row(Row& r) {
    r.a = r.b = r.c = r.d = r.e = 0ull;
}

__device__ __forceinline__ void epilogue_row(const Row& a, int b, int c,
                                             const float* __restrict__ y,
                                             float* __restrict__ out) {
    const float* yb = y + (size_t)b * NE;
    ull v[5] = {a.a, a.b, a.c, a.d, a.e};
    float res = 0.f;
    #pragma unroll
    for (int k = 0; k < 5; k++) {
        float lo, hi;
        asm("mov.b64 {%0, %1}, %2;" : "=f"(lo), "=f"(hi) : "l"(v[k]));
        res += lo * yb[2*k];
        res += hi * yb[2*k + 1];
    }
    out[(size_t)b * NC + c] = res;
}

// ---------------------------------------------------------------------------
// Main kernel: 2-level Horner (middle level folded into acc via the pair
// monomial x_p*x_q) to keep live registers under the 168 cap at ROWS=4.
//   acc += x_p*M1[p]
//   s    = M2[p,q] + sum_{i>=q} x_i*M3[p,q,i]
//   acc += (x_p*x_q)*s
// ---------------------------------------------------------------------------
__global__ __launch_bounds__(TPB, 3)
void contract_kernel(const float* __restrict__ x, const float* __restrict__ y,
                     float* __restrict__ out) {
    __shared__ __align__(16) float sM[NBASIS * MROW];

    const int c   = blockIdx.y;
    const int b0  = blockIdx.x * (TPB * ROWS);
    const int tid = threadIdx.x;

    // Stage M[c] into shared (float4, broadcast-reused by all warps).
    {
        const float4* src = reinterpret_cast<const float4*>(g_M + (size_t)c * NBASIS * MROW);
        float4* dst = reinterpret_cast<float4*>(sM);
        const int n4 = NBASIS * MROW / 4;   // 2904
        for (int j = tid; j < n4; j += TPB) dst[j] = src[j];
    }

    // Load the thread's four x rows straight into registers.
    float xv[ROWS][NL];
    #pragma unroll
    for (int r = 0; r < ROWS; r++) {
        const float4* xr = reinterpret_cast<const float4*>(
            x + ((size_t)(b0 + r * TPB + tid) * NC + c) * NL);
        #pragma unroll
        for (int j = 0; j < 4; j++) {
            float4 v = xr[j];
            xv[r][4*j+0] = v.x; xv[r][4*j+1] = v.y;
            xv[r][4*j+2] = v.z; xv[r][4*j+3] = v.w;
        }
    }
    __syncthreads();

    Row acc[ROWS];
    #pragma unroll
    for (int r = 0; r < ROWS; r++) zero_row(acc[r]);

    const float* mp = sM;
    #pragma unroll
    for (int p = 0; p < NL; p++) {
        // acc += x_p * M1[p]
        {
            Row m1 = load_row(mp);
            mp += MROW;
            #pragma unroll
            for (int r = 0; r < ROWS; r++)
                fma_row(acc[r], dup2(xv[r][p]), m1);
        }
        #pragma unroll
        for (int q = p; q < NL; q++) {
            Row s[ROWS];
            {
                Row m2 = load_row(mp);   // M2[p,q]
                mp += MROW;
                #pragma unroll
                for (int r = 0; r < ROWS; r++) s[r] = m2;
            }
            #pragma unroll
            for (int i = q; i < NL; i++) {
                Row m3 = load_row(mp);
                mp += MROW;
                #pragma unroll
                for (int r = 0; r < ROWS; r++)
                    fma_row(s[r], dup2(xv[r][i]), m3);
            }
            #pragma unroll
            for (int r = 0; r < ROWS; r++)
                fma_row(acc[r], dup2(xv[r][p] * xv[r][q]), s[r]);
        }
    }

    #pragma unroll
    for (int r = 0; r < ROWS; r++)
        epilogue_row(acc[r], b0 + r * TPB + tid, c, y, out);
}

// ---------------------------------------------------------------------------
extern "C" void kernel_launch(void* const* d_in, const int* in_sizes, int n_in,
                              void* d_out, int out_size) {
    const float *x = 0, *y = 0, *U1 = 0, *U2 = 0, *U3 = 0, *W1 = 0, *W2 = 0, *W3 = 0;
    for (int i = 0; i < n_in; i++) {
        const float* p = (const float*)d_in[i];
        switch (in_sizes[i]) {
            case 8192 * 128 * 16:   x  = p; break;   // (B,C,L)
            case 8192 * 10:         y  = p; break;   // (B,E)
            case 16:                U1 = p; break;   // (L,K1)
            case 16 * 16 * 4:       U2 = p; break;   // (L,L,K2)
            case 16 * 16 * 16 * 23: U3 = p; break;   // (L,L,L,K3)
            case 10 * 1 * 128:      W1 = p; break;   // (E,K1,C)
            case 10 * 4 * 128:      W2 = p; break;   // (E,K2,C)
            case 10 * 23 * 128:     W3 = p; break;   // (E,K3,C)
        }
    }

    const int tot = NBASIS * NC;
    build_M_kernel<<<(tot + 255) / 256, 256>>>(U1, U2, U3, W1, W2, W3);

    dim3 grid(NB_TOT / (TPB * ROWS), NC);   // (16, 128)
    contract_kernel<<<grid, TPB>>>(x, y, (float*)d_out);
}